// round 1
// baseline (speedup 1.0000x reference)
#include <cuda_runtime.h>

typedef unsigned long long ull;

#define BN 8192
#define TN 2048

// Transposed excitation scratch: [T][B] layout for coalesced per-step loads.
__device__ float g_excT[(size_t)TN * BN];

__device__ __forceinline__ float tanha(float x) {
    float y; asm("tanh.approx.f32 %0, %1;" : "=f"(y) : "f"(x)); return y;
}
__device__ __forceinline__ ull pack2(float lo, float hi) {
    ull r; asm("mov.b64 %0, {%1, %2};" : "=l"(r) : "f"(lo), "f"(hi)); return r;
}
__device__ __forceinline__ void unpack2(ull v, float& lo, float& hi) {
    asm("mov.b64 {%0, %1}, %2;" : "=f"(lo), "=f"(hi) : "l"(v));
}
// Packed dual-FMA (Blackwell f32x2 pipe — 2 fp32 FMAs per issue).
__device__ __forceinline__ void ffma2(ull& d, ull a, ull b) {
    asm("fma.rn.f32x2 %0, %1, %2, %0;" : "+l"(d) : "l"(a), "l"(b));
}

// exc[B][T] -> g_excT[T][B]
__global__ void transpose_exc(const float* __restrict__ exc) {
    __shared__ float tile[32][33];
    int t0 = blockIdx.x * 32, b0 = blockIdx.y * 32;
    int tx = threadIdx.x, ty = threadIdx.y;
#pragma unroll
    for (int i = 0; i < 32; i += 8)
        tile[ty + i][tx] = exc[(size_t)(b0 + ty + i) * TN + t0 + tx];
    __syncthreads();
#pragma unroll
    for (int i = 0; i < 32; i += 8)
        g_excT[(size_t)(t0 + ty + i) * BN + b0 + tx] = tile[tx][ty + i];
}

// 4 threads per muscle (lane quads). 32-thread CTAs -> 8 muscles/CTA,
// 1024 CTAs, 1024 warps (~7/SM) — all resident in one wave.
__global__ __launch_bounds__(32) void ode_kernel(
    const float* __restrict__ init, const float* __restrict__ tspan,
    const float* __restrict__ W1, const float* __restrict__ b1,
    const float* __restrict__ W2, const float* __restrict__ b2,
    const float* __restrict__ W3, const float* __restrict__ b3,
    float* __restrict__ out)
{
    __shared__ __align__(16) float sW1[256];
    __shared__ __align__(16) float sb1[64];
    __shared__ __align__(16) float sW2[4096];
    __shared__ __align__(16) float sb2[64];
    __shared__ __align__(16) float sW3[192];
    __shared__ __align__(16) float sb3[4];
    __shared__ __align__(16) float sTs[TN];

    int tid = threadIdx.x;
    for (int i = tid; i < 256;  i += 32) sW1[i] = W1[i];
    for (int i = tid; i < 64;   i += 32) sb1[i] = b1[i];
    for (int i = tid; i < 4096; i += 32) sW2[i] = W2[i];
    for (int i = tid; i < 64;   i += 32) sb2[i] = b2[i];
    for (int i = tid; i < 192;  i += 32) sW3[i] = W3[i];
    if (tid < 4) sb3[tid] = (tid < 3) ? b3[tid] : 0.0f;
    for (int i = tid; i < TN;   i += 32) sTs[i] = tspan[i];
    __syncthreads();

    const int sub = tid & 3;          // which 16-neuron block this thread owns
    const int grp = tid & ~3;         // lane-quad base
    const int b   = blockIdx.x * 8 + (tid >> 2);

    float y0 = init[b * 3 + 0];
    float y1 = init[b * 3 + 1];
    float y2 = init[b * 3 + 2];
    if (sub == 0) { out[b*3+0] = y0; out[b*3+1] = y1; out[b*3+2] = y2; }

    // k1 at step 0 uses exc[:, 0] (searchsorted idx = clip(-1) = 0)
    float ep = g_excT[b];

#pragma unroll 1
    for (int it = 0; it < TN - 1; it++) {
        float ec  = g_excT[(size_t)it * BN + b];   // exc[:, it] for k2/k3/k4
        float dt  = sTs[it + 1] - sTs[it];
        float hd  = 0.5f * dt;
        float a0 = y0, a1 = y1, a2 = y2;
        float s0 = 0.f, s1 = 0.f, s2 = 0.f;

#pragma unroll 1
        for (int s = 0; s < 4; s++) {
            float e = (s == 0) ? ep : ec;

            // ---------------- physics_rhs (clipped state) ----------------
            float lM   = fminf(fmaxf(a0, 0.0445f), 0.1424f);
            float act  = fminf(fmaxf(a1, 0.01f), 1.0f);
            float fat  = fminf(fmaxf(a2, 0.0f), 1.0f);
            float aeff = act * (1.0f - fat);
            // L0*sin(PENN0) = 0.089*sin(0.0873)
            float sinp = fminf(__fdividef(0.00775983457f, lM), 0.99f);
            float cosp = sqrtf(1.0f - sinp * sinp);
            // LMT_DEFAULT = 0.126 + 0.089*cos(0.0873)
            float lT   = 0.214661068f - lM * cosp;
            float epsT = (lT - 0.126f) * (1.0f / 0.126f);
            float fT   = (epsT > 0.0f) ? 0.2f * (__expf(35.0f * epsT) - 1.0f) : 0.0f;
            float lN   = lM * (1.0f / 0.089f);
            float ddv  = lN - 1.0f;
            float fL   = __expf(-ddv * ddv * (1.0f / 0.45f));
            float fPE  = (lN > 1.0f)
                       ? (__expf(ddv * (5.0f / 0.6f)) - 1.0f) * (1.0f / 147.4131591f)
                       : 0.0f;
            float fV   = __fdividef(__fdividef(fT, cosp) - fPE, aeff * fL + 0.001f);
            float vN   = fminf(fmaxf(__fdividef(fV - 1.0f, 1.0f + fabsf(fV) * 4.0f),
                                     -1.0f), 1.5f);
            float k0   = 0.89f * vN;                       // VMAX*L0*vN
            float tau  = (e > act) ? 0.01f * (0.5f + 1.5f * act)
                                   : __fdividef(0.04f, 0.5f + 1.5f * act);
            float k1d  = __fdividef(e - act, tau);
            float k2d  = 0.01f * aeff * (1.0f - fat) - 0.002f * (1.0f - aeff) * fat;

            // ---------------- neural correction (raw state) ----------------
            // layer 1: each thread computes 16 of 64 hidden units
            float h[16];
#pragma unroll
            for (int j = 0; j < 16; j++) {
                int J = sub * 16 + j;
                float acc = sb1[J];
                acc = fmaf(a0, sW1[J],       acc);
                acc = fmaf(a1, sW1[64 + J],  acc);
                acc = fmaf(a2, sW1[128 + J], acc);
                acc = fmaf(e,  sW1[192 + J], acc);
                h[j] = tanha(acc);
            }
            // layer 2: 16 outputs per thread, 8 packed f32x2 accumulators;
            // hidden vector broadcast across the lane-quad via shuffles.
            ull acc2[8];
            {
                const ull* bp = (const ull*)(sb2 + sub * 16);
#pragma unroll
                for (int j = 0; j < 8; j++) acc2[j] = bp[j];
            }
#pragma unroll 1
            for (int kb = 0; kb < 4; kb++) {
                int src = grp + kb;
#pragma unroll
                for (int kk = 0; kk < 16; kk++) {
                    float hk = __shfl_sync(0xffffffffu, h[kk], src);
                    ull hh = pack2(hk, hk);
                    const ull* w = (const ull*)(sW2 + (kb * 16 + kk) * 64 + sub * 16);
#pragma unroll
                    for (int j = 0; j < 8; j++) ffma2(acc2[j], hh, w[j]);
                }
            }
            // layer 3 partials + quad reduction
            float p0 = 0.f, p1 = 0.f, p2 = 0.f;
#pragma unroll
            for (int j = 0; j < 8; j++) {
                float lo, hi; unpack2(acc2[j], lo, hi);
                lo = tanha(lo); hi = tanha(hi);
                int J = sub * 16 + 2 * j;
                p0 = fmaf(lo, sW3[J * 3 + 0], p0);
                p0 = fmaf(hi, sW3[J * 3 + 3], p0);
                p1 = fmaf(lo, sW3[J * 3 + 1], p1);
                p1 = fmaf(hi, sW3[J * 3 + 4], p1);
                p2 = fmaf(lo, sW3[J * 3 + 2], p2);
                p2 = fmaf(hi, sW3[J * 3 + 5], p2);
            }
            p0 += __shfl_xor_sync(0xffffffffu, p0, 1);
            p0 += __shfl_xor_sync(0xffffffffu, p0, 2);
            p1 += __shfl_xor_sync(0xffffffffu, p1, 1);
            p1 += __shfl_xor_sync(0xffffffffu, p1, 2);
            p2 += __shfl_xor_sync(0xffffffffu, p2, 1);
            p2 += __shfl_xor_sync(0xffffffffu, p2, 2);

            k0  += 0.2f * (0.1f * tanha(p0 + sb3[0]));
            k1d += 0.2f * (0.1f * tanha(p1 + sb3[1]));
            k2d += 0.2f * (0.1f * tanha(p2 + sb3[2]));

            // ---------------- RK4 combine ----------------
            float wgt = (s == 1 || s == 2) ? 2.0f : 1.0f;
            s0 = fmaf(wgt, k0,  s0);
            s1 = fmaf(wgt, k1d, s1);
            s2 = fmaf(wgt, k2d, s2);
            float st = (s < 2) ? hd : dt;   // stage input offsets (s==3 unused)
            a0 = y0 + st * k0;
            a1 = y1 + st * k1d;
            a2 = y2 + st * k2d;
        }

        float w6 = dt * (1.0f / 6.0f);
        y0 += w6 * s0; y1 += w6 * s1; y2 += w6 * s2;

        if (sub == 0) {
            size_t o = (size_t)(it + 1) * (BN * 3) + (size_t)b * 3;
            out[o] = y0; out[o + 1] = y1; out[o + 2] = y2;
        }
        ep = ec;
    }
}

extern "C" void kernel_launch(void* const* d_in, const int* in_sizes, int n_in,
                              void* d_out, int out_size) {
    const float* init = (const float*)d_in[0];
    const float* exc  = (const float*)d_in[1];
    const float* ts   = (const float*)d_in[2];
    const float* W1   = (const float*)d_in[3];
    const float* b1   = (const float*)d_in[4];
    const float* W2   = (const float*)d_in[5];
    const float* b2   = (const float*)d_in[6];
    const float* W3   = (const float*)d_in[7];
    const float* b3   = (const float*)d_in[8];
    float* out = (float*)d_out;

    dim3 tb(32, 8);
    dim3 tg(TN / 32, BN / 32);
    transpose_exc<<<tg, tb>>>(exc);
    ode_kernel<<<BN / 8, 32>>>(init, ts, W1, b1, W2, b2, W3, b3, out);
}